// round 7
// baseline (speedup 1.0000x reference)
#include <cuda_runtime.h>

// Problem dimensions (fixed by the reference setup)
#define BB 4
#define LL 4096
#define DD 128
#define NN 16
#define TT 32               // chunk length
#define NC (LL / TT)        // 128 chunks per batch
#define DT_OFF 0.1f

typedef unsigned long long u64;

// Scratch (device globals — no allocation allowed)
__device__ __align__(16) float g_coef[BB * LL * 48];      // [b][l][e0..15,w0..15,C0..15]
__device__ __align__(16) float g_E[BB * NC * DD * NN];    // chunk-local end states
__device__ __align__(16) float g_H0[BB * NC * DD * NN];   // carry-in state per chunk
__device__ float g_P[BB * NC * NN];                        // chunk decay products

// ---------------- packed f32x2 helpers ----------------
__device__ __forceinline__ u64 fma2(u64 a, u64 b, u64 c) {
    u64 d; asm("fma.rn.f32x2 %0, %1, %2, %3;" : "=l"(d) : "l"(a), "l"(b), "l"(c));
    return d;
}
__device__ __forceinline__ u64 mul2(u64 a, u64 b) {
    u64 d; asm("mul.rn.f32x2 %0, %1, %2;" : "=l"(d) : "l"(a), "l"(b));
    return d;
}
__device__ __forceinline__ u64 pack2(float lo, float hi) {
    u64 d;
    asm("mov.b64 %0, {%1, %2};" : "=l"(d)
        : "r"(__float_as_uint(lo)), "r"(__float_as_uint(hi)));
    return d;
}
__device__ __forceinline__ float2 unpack2(u64 v) {
    unsigned int lo, hi;
    asm("mov.b64 {%0, %1}, %2;" : "=r"(lo), "=r"(hi) : "l"(v));
    return make_float2(__uint_as_float(lo), __uint_as_float(hi));
}

// ---------------------------------------------------------------------------
// K1: per-(b,l) coefficients. 33 dot products of length 128 per position.
// Two threads per position (64 dims each), inner math packed f32x2 along k.
// ---------------------------------------------------------------------------
__global__ __launch_bounds__(128) void k1_coef(
    const float* __restrict__ x,
    const float* __restrict__ A,
    const float* __restrict__ Wb, const float* __restrict__ bb,
    const float* __restrict__ Wc, const float* __restrict__ bc,
    const float* __restrict__ Wd, const float* __restrict__ bd)
{
    __shared__ __align__(16) float sW[33 * 128];
    __shared__ float sb[33];
    __shared__ float sA[16];

    int tid = threadIdx.x;
    for (int i = tid; i < 2048; i += 128) {
        sW[i]        = Wb[i];
        sW[2048 + i] = Wc[i];
    }
    sW[4096 + tid] = Wd[tid];
    if (tid < 16) { sb[tid] = bb[tid]; sb[16 + tid] = bc[tid]; sA[tid] = A[tid]; }
    if (tid == 0) sb[32] = bd[0];
    __syncthreads();

    int g    = blockIdx.x * 128 + tid;       // 0..32767
    int pos  = g >> 1;                        // (b*L + l)
    int half = g & 1;                         // which 64-dim half of the dot

    u64 acc[33];
#pragma unroll
    for (int j = 0; j < 33; j++) acc[j] = 0ull;   // (0.f, 0.f)

    const ulonglong2* xr = (const ulonglong2*)(x + (size_t)pos * DD + half * 64);
    const ulonglong2* W2 = (const ulonglong2*)sW;

#pragma unroll 4
    for (int kk = 0; kk < 16; kk++) {
        ulonglong2 xv = xr[kk];
        int basei = half * 16 + kk;
#pragma unroll
        for (int j = 0; j < 33; j++) {
            ulonglong2 wv = W2[j * 32 + basei];
            acc[j] = fma2(xv.x, wv.x, acc[j]);
            acc[j] = fma2(xv.y, wv.y, acc[j]);
        }
    }

    float s[33];
#pragma unroll
    for (int j = 0; j < 33; j++) {
        float2 p = unpack2(acc[j]);
        s[j] = p.x + p.y;
        s[j] += __shfl_down_sync(0xffffffffu, s[j], 1);
    }

    if (half == 0) {
        float z = s[32] + sb[32];
        // stable softplus matching jax.nn.softplus
        float delta = fmaxf(z, 0.f) + log1pf(expf(-fabsf(z))) + DT_OFF;

        float out[48];
#pragma unroll
        for (int n = 0; n < 16; n++) {
            float da = delta * sA[n];
            out[n]      = expf(da);
            out[16 + n] = (1.0f - expf(-da)) * delta * (s[n] + sb[n]);
            out[32 + n] = s[16 + n] + sb[16 + n];
        }
        float4* o = (float4*)(g_coef + (size_t)pos * 48);
        const float4* ov = (const float4*)out;
#pragma unroll
        for (int i = 0; i < 12; i++) o[i] = ov[i];
    }
}

// ---------------------------------------------------------------------------
// K2: chunk-local scan, h=0 init. Block=(chunk c, batch b), thread=d.
// State packed as 8 f32x2 over n-pairs. x chunk staged in shared.
// ---------------------------------------------------------------------------
__global__ __launch_bounds__(128) void k2_local(const float* __restrict__ x)
{
    __shared__ __align__(16) float sc[TT * 48];
    __shared__ __align__(16) float sx[TT * DD];
    int c = blockIdx.x, b = blockIdx.y, d = threadIdx.x;

    const float4* csrc = (const float4*)(g_coef + (size_t)(b * LL + c * TT) * 48);
    float4* cdst = (float4*)sc;
#pragma unroll
    for (int i = 0; i < 3; i++) cdst[d + 128 * i] = csrc[d + 128 * i];

    const float4* xsrc = (const float4*)(x + (size_t)(b * LL + c * TT) * DD);
    float4* xdst = (float4*)sx;
#pragma unroll
    for (int i = 0; i < 8; i++) xdst[d + 128 * i] = xsrc[d + 128 * i];
    __syncthreads();

    u64 h[8];
#pragma unroll
    for (int i = 0; i < 8; i++) h[i] = 0ull;

#pragma unroll 4
    for (int t = 0; t < TT; t++) {
        float xt = sx[t * DD + d];
        u64 x2 = pack2(xt, xt);
        const ulonglong2* row = (const ulonglong2*)(sc + t * 48);
#pragma unroll
        for (int i = 0; i < 4; i++) {
            ulonglong2 e2 = row[i];
            ulonglong2 w2 = row[4 + i];
            h[2 * i]     = fma2(e2.x, h[2 * i],     mul2(w2.x, x2));
            h[2 * i + 1] = fma2(e2.y, h[2 * i + 1], mul2(w2.y, x2));
        }
    }

    ulonglong2* Eo = (ulonglong2*)(g_E + (size_t)((b * NC + c) * DD + d) * NN);
#pragma unroll
    for (int i = 0; i < 4; i++) {
        ulonglong2 v; v.x = h[2 * i]; v.y = h[2 * i + 1];
        Eo[i] = v;
    }

    if (d < 16) {
        float p = 1.f;
#pragma unroll
        for (int t = 0; t < TT; t++) p *= sc[t * 48 + d];
        g_P[(b * NC + c) * NN + d] = p;
    }
}

// ---------------------------------------------------------------------------
// K2.5: inter-chunk combine. One thread per (b,d,n); sequential over chunks:
//   H0[c] = h;  h = P[c]*h + E[c]
// ---------------------------------------------------------------------------
__global__ void k25_combine()
{
    int idx = blockIdx.x * blockDim.x + threadIdx.x;  // 0..8191
    int b = idx >> 11;          // / (D*N)
    int r = idx & 2047;         // d*16 + n
    int n = r & 15;
    float h = 0.f;
    const float* __restrict__ P = g_P + b * NC * NN + n;
    const float* __restrict__ E = g_E;
    float* __restrict__ H0 = g_H0;
    size_t o = (size_t)b * NC * (DD * NN) + r;
#pragma unroll 8
    for (int c = 0; c < NC; c++) {
        H0[o] = h;
        h = fmaf(P[c * NN], h, E[o]);
        o += DD * NN;
    }
}

// ---------------------------------------------------------------------------
// K3: final scan with carry-in, emits y[b,l,d] = sum_n C[l,n]*h[n].
// ---------------------------------------------------------------------------
__global__ __launch_bounds__(128) void k3_scan(const float* __restrict__ x,
                                               float* __restrict__ y)
{
    __shared__ __align__(16) float sc[TT * 48];
    __shared__ __align__(16) float sx[TT * DD];
    int c = blockIdx.x, b = blockIdx.y, d = threadIdx.x;

    const float4* csrc = (const float4*)(g_coef + (size_t)(b * LL + c * TT) * 48);
    float4* cdst = (float4*)sc;
#pragma unroll
    for (int i = 0; i < 3; i++) cdst[d + 128 * i] = csrc[d + 128 * i];

    const float4* xsrc = (const float4*)(x + (size_t)(b * LL + c * TT) * DD);
    float4* xdst = (float4*)sx;
#pragma unroll
    for (int i = 0; i < 8; i++) xdst[d + 128 * i] = xsrc[d + 128 * i];

    u64 h[8];
    const ulonglong2* hi = (const ulonglong2*)(g_H0 + (size_t)((b * NC + c) * DD + d) * NN);
#pragma unroll
    for (int i = 0; i < 4; i++) {
        ulonglong2 v = hi[i];
        h[2 * i] = v.x; h[2 * i + 1] = v.y;
    }
    __syncthreads();

    float* yp = y + (size_t)(b * LL + c * TT) * DD + d;

#pragma unroll 4
    for (int t = 0; t < TT; t++) {
        float xt = sx[t * DD + d];
        u64 x2 = pack2(xt, xt);
        const ulonglong2* row = (const ulonglong2*)(sc + t * 48);

        u64 a0 = 0ull, a1 = 0ull, a2 = 0ull, a3 = 0ull;
#pragma unroll
        for (int i = 0; i < 4; i++) {
            ulonglong2 e2 = row[i];
            ulonglong2 w2 = row[4 + i];
            ulonglong2 c2 = row[8 + i];
            h[2 * i]     = fma2(e2.x, h[2 * i],     mul2(w2.x, x2));
            h[2 * i + 1] = fma2(e2.y, h[2 * i + 1], mul2(w2.y, x2));
            if (i == 0)      { a0 = fma2(c2.x, h[0], a0); a1 = fma2(c2.y, h[1], a1); }
            else if (i == 1) { a2 = fma2(c2.x, h[2], a2); a3 = fma2(c2.y, h[3], a3); }
            else if (i == 2) { a0 = fma2(c2.x, h[4], a0); a1 = fma2(c2.y, h[5], a1); }
            else             { a2 = fma2(c2.x, h[6], a2); a3 = fma2(c2.y, h[7], a3); }
        }
        float2 p0 = unpack2(a0), p1 = unpack2(a1), p2 = unpack2(a2), p3 = unpack2(a3);
        yp[t * DD] = ((p0.x + p0.y) + (p1.x + p1.y)) + ((p2.x + p2.y) + (p3.x + p3.y));
    }
}

// ---------------------------------------------------------------------------
extern "C" void kernel_launch(void* const* d_in, const int* in_sizes, int n_in,
                              void* d_out, int out_size)
{
    const float* x  = (const float*)d_in[0];
    const float* A  = (const float*)d_in[1];
    const float* Wb = (const float*)d_in[2];
    const float* bb = (const float*)d_in[3];
    const float* Wc = (const float*)d_in[4];
    const float* bc = (const float*)d_in[5];
    const float* Wd = (const float*)d_in[6];
    const float* bd = (const float*)d_in[7];
    float* y = (float*)d_out;

    k1_coef<<<256, 128>>>(x, A, Wb, bb, Wc, bc, Wd, bd);

    dim3 grid(NC, BB);
    k2_local<<<grid, 128>>>(x);
    k25_combine<<<32, 256>>>();
    k3_scan<<<grid, 128>>>(x, y);
}

// round 8
// speedup vs baseline: 1.0319x; 1.0319x over previous
#include <cuda_runtime.h>

// Problem dimensions (fixed by the reference setup)
#define BB 4
#define LL 4096
#define DD 128
#define NN 16
#define TT 32               // chunk length
#define NC (LL / TT)        // 128 chunks per batch
#define DT_OFF 0.1f

typedef unsigned long long u64;

// Scratch (device globals — no allocation allowed)
__device__ __align__(16) float g_coef[BB * LL * 48];      // [b][l][e0..15,w0..15,C0..15]
__device__ __align__(16) float g_E[BB * NC * DD * NN];    // chunk-local end states
__device__ __align__(16) float g_H0[BB * NC * DD * NN];   // carry-in state per chunk
__device__ float g_P[BB * NC * NN];                        // chunk decay products

// ---------------- packed f32x2 helpers ----------------
__device__ __forceinline__ u64 fma2(u64 a, u64 b, u64 c) {
    u64 d; asm("fma.rn.f32x2 %0, %1, %2, %3;" : "=l"(d) : "l"(a), "l"(b), "l"(c));
    return d;
}
__device__ __forceinline__ u64 mul2(u64 a, u64 b) {
    u64 d; asm("mul.rn.f32x2 %0, %1, %2;" : "=l"(d) : "l"(a), "l"(b));
    return d;
}
__device__ __forceinline__ u64 pack2(float lo, float hi) {
    u64 d;
    asm("mov.b64 %0, {%1, %2};" : "=l"(d)
        : "r"(__float_as_uint(lo)), "r"(__float_as_uint(hi)));
    return d;
}
__device__ __forceinline__ float2 unpack2(u64 v) {
    unsigned int lo, hi;
    asm("mov.b64 {%0, %1}, %2;" : "=r"(lo), "=r"(hi) : "l"(v));
    return make_float2(__uint_as_float(lo), __uint_as_float(hi));
}

// ---------------------------------------------------------------------------
// K1: per-(b,l) coefficients. 33 dot products of length 128 per position.
// FOUR threads per position (32 dims each), scalar FFMA, kk-rotation by 2*q
// so the four dim-slices hit distinct mod-8 float4 offsets in shared W
// (conflict-free LDS). Combined via two shfl_down steps.
// ---------------------------------------------------------------------------
__global__ __launch_bounds__(128) void k1_coef(
    const float* __restrict__ x,
    const float* __restrict__ A,
    const float* __restrict__ Wb, const float* __restrict__ bb,
    const float* __restrict__ Wc, const float* __restrict__ bc,
    const float* __restrict__ Wd, const float* __restrict__ bd)
{
    __shared__ __align__(16) float sW[33 * 128];
    __shared__ float sb[33];
    __shared__ float sA[16];

    int tid = threadIdx.x;
    for (int i = tid; i < 2048; i += 128) {
        sW[i]        = Wb[i];
        sW[2048 + i] = Wc[i];
    }
    sW[4096 + tid] = Wd[tid];
    if (tid < 16) { sb[tid] = bb[tid]; sb[16 + tid] = bc[tid]; sA[tid] = A[tid]; }
    if (tid == 0) sb[32] = bd[0];
    __syncthreads();

    int g   = blockIdx.x * 128 + tid;        // 0..65535
    int pos = g >> 2;                         // (b*L + l)
    int q   = g & 3;                          // quarter of the 128-dim dot

    float acc[33];
#pragma unroll
    for (int j = 0; j < 33; j++) acc[j] = 0.f;

    const float4* xr = (const float4*)(x + (size_t)pos * DD + q * 32);
    const float4* W4 = (const float4*)sW;

#pragma unroll
    for (int kk = 0; kk < 8; kk++) {
        int kkr = (kk + 2 * q) & 7;           // rotate -> conflict-free banks
        float4 xv = xr[kkr];
        int basei = q * 8 + kkr;
#pragma unroll
        for (int j = 0; j < 33; j++) {
            float4 wv = W4[j * 32 + basei];
            acc[j] = fmaf(xv.w, wv.w, fmaf(xv.z, wv.z,
                     fmaf(xv.y, wv.y, fmaf(xv.x, wv.x, acc[j]))));
        }
    }
#pragma unroll
    for (int j = 0; j < 33; j++) {
        acc[j] += __shfl_down_sync(0xffffffffu, acc[j], 2);
        acc[j] += __shfl_down_sync(0xffffffffu, acc[j], 1);
    }

    if (q == 0) {
        float z = acc[32] + sb[32];
        // stable softplus matching jax.nn.softplus
        float delta = fmaxf(z, 0.f) + log1pf(expf(-fabsf(z))) + DT_OFF;

        float out[48];
#pragma unroll
        for (int n = 0; n < 16; n++) {
            float da = delta * sA[n];
            out[n]      = expf(da);
            out[16 + n] = (1.0f - expf(-da)) * delta * (acc[n] + sb[n]);
            out[32 + n] = acc[16 + n] + sb[16 + n];
        }
        float4* o = (float4*)(g_coef + (size_t)pos * 48);
        const float4* ov = (const float4*)out;
#pragma unroll
        for (int i = 0; i < 12; i++) o[i] = ov[i];
    }
}

// ---------------------------------------------------------------------------
// K2: chunk-local scan, h=0 init. Block=(chunk c, batch b), thread=d.
// State packed as 8 f32x2 over n-pairs; x column held in registers
// (32 coalesced front-batched LDGs), coef rows broadcast from shared.
// ---------------------------------------------------------------------------
__global__ __launch_bounds__(128) void k2_local(const float* __restrict__ x)
{
    __shared__ __align__(16) float sc[TT * 48];
    int c = blockIdx.x, b = blockIdx.y, d = threadIdx.x;

    // front-batched x loads: thread d's column of the chunk
    float xv[TT];
    const float* xp = x + (size_t)(b * LL + c * TT) * DD + d;
#pragma unroll
    for (int t = 0; t < TT; t++) xv[t] = xp[t * DD];

    const float4* csrc = (const float4*)(g_coef + (size_t)(b * LL + c * TT) * 48);
    float4* cdst = (float4*)sc;
#pragma unroll
    for (int i = 0; i < 3; i++) cdst[d + 128 * i] = csrc[d + 128 * i];
    __syncthreads();

    u64 h[8];
#pragma unroll
    for (int i = 0; i < 8; i++) h[i] = 0ull;

#pragma unroll 4
    for (int t = 0; t < TT; t++) {
        u64 x2 = pack2(xv[t], xv[t]);
        const ulonglong2* row = (const ulonglong2*)(sc + t * 48);
#pragma unroll
        for (int i = 0; i < 4; i++) {
            ulonglong2 e2 = row[i];
            ulonglong2 w2 = row[4 + i];
            h[2 * i]     = fma2(e2.x, h[2 * i],     mul2(w2.x, x2));
            h[2 * i + 1] = fma2(e2.y, h[2 * i + 1], mul2(w2.y, x2));
        }
    }

    ulonglong2* Eo = (ulonglong2*)(g_E + (size_t)((b * NC + c) * DD + d) * NN);
#pragma unroll
    for (int i = 0; i < 4; i++) {
        ulonglong2 v; v.x = h[2 * i]; v.y = h[2 * i + 1];
        Eo[i] = v;
    }

    if (d < 16) {
        float p = 1.f;
#pragma unroll
        for (int t = 0; t < TT; t++) p *= sc[t * 48 + d];
        g_P[(b * NC + c) * NN + d] = p;
    }
}

// ---------------------------------------------------------------------------
// K2.5: inter-chunk combine. One thread per (b,d,n); sequential over chunks:
//   H0[c] = h;  h = P[c]*h + E[c].  Deep unroll -> batched independent loads.
// ---------------------------------------------------------------------------
__global__ __launch_bounds__(128) void k25_combine()
{
    int idx = blockIdx.x * 128 + threadIdx.x;  // 0..8191
    int b = idx >> 11;          // / (D*N)
    int r = idx & 2047;         // d*16 + n
    int n = r & 15;
    float h = 0.f;
    const float* __restrict__ P = g_P + b * NC * NN + n;
    const float* __restrict__ E = g_E;
    float* __restrict__ H0 = g_H0;
    size_t o = (size_t)b * NC * (DD * NN) + r;
#pragma unroll 16
    for (int c = 0; c < NC; c++) {
        H0[o] = h;
        h = fmaf(P[c * NN], h, E[o]);
        o += DD * NN;
    }
}

// ---------------------------------------------------------------------------
// K3: final scan with carry-in, emits y[b,l,d] = sum_n C[l,n]*h[n].
// ---------------------------------------------------------------------------
__global__ __launch_bounds__(128) void k3_scan(const float* __restrict__ x,
                                               float* __restrict__ y)
{
    __shared__ __align__(16) float sc[TT * 48];
    int c = blockIdx.x, b = blockIdx.y, d = threadIdx.x;

    // front-batched x loads
    float xv[TT];
    const float* xp = x + (size_t)(b * LL + c * TT) * DD + d;
#pragma unroll
    for (int t = 0; t < TT; t++) xv[t] = xp[t * DD];

    const float4* csrc = (const float4*)(g_coef + (size_t)(b * LL + c * TT) * 48);
    float4* cdst = (float4*)sc;
#pragma unroll
    for (int i = 0; i < 3; i++) cdst[d + 128 * i] = csrc[d + 128 * i];

    u64 h[8];
    const ulonglong2* hi = (const ulonglong2*)(g_H0 + (size_t)((b * NC + c) * DD + d) * NN);
#pragma unroll
    for (int i = 0; i < 4; i++) {
        ulonglong2 v = hi[i];
        h[2 * i] = v.x; h[2 * i + 1] = v.y;
    }
    __syncthreads();

    float* yp = y + (size_t)(b * LL + c * TT) * DD + d;

#pragma unroll 4
    for (int t = 0; t < TT; t++) {
        u64 x2 = pack2(xv[t], xv[t]);
        const ulonglong2* row = (const ulonglong2*)(sc + t * 48);

        u64 a0 = 0ull, a1 = 0ull, a2 = 0ull, a3 = 0ull;
#pragma unroll
        for (int i = 0; i < 4; i++) {
            ulonglong2 e2 = row[i];
            ulonglong2 w2 = row[4 + i];
            ulonglong2 c2 = row[8 + i];
            h[2 * i]     = fma2(e2.x, h[2 * i],     mul2(w2.x, x2));
            h[2 * i + 1] = fma2(e2.y, h[2 * i + 1], mul2(w2.y, x2));
            if (i == 0)      { a0 = fma2(c2.x, h[0], a0); a1 = fma2(c2.y, h[1], a1); }
            else if (i == 1) { a2 = fma2(c2.x, h[2], a2); a3 = fma2(c2.y, h[3], a3); }
            else if (i == 2) { a0 = fma2(c2.x, h[4], a0); a1 = fma2(c2.y, h[5], a1); }
            else             { a2 = fma2(c2.x, h[6], a2); a3 = fma2(c2.y, h[7], a3); }
        }
        float2 p0 = unpack2(a0), p1 = unpack2(a1), p2 = unpack2(a2), p3 = unpack2(a3);
        yp[t * DD] = ((p0.x + p0.y) + (p1.x + p1.y)) + ((p2.x + p2.y) + (p3.x + p3.y));
    }
}

// ---------------------------------------------------------------------------
extern "C" void kernel_launch(void* const* d_in, const int* in_sizes, int n_in,
                              void* d_out, int out_size)
{
    const float* x  = (const float*)d_in[0];
    const float* A  = (const float*)d_in[1];
    const float* Wb = (const float*)d_in[2];
    const float* bb = (const float*)d_in[3];
    const float* Wc = (const float*)d_in[4];
    const float* bc = (const float*)d_in[5];
    const float* Wd = (const float*)d_in[6];
    const float* bd = (const float*)d_in[7];
    float* y = (float*)d_out;

    // K1: 4 threads per (b,l) position -> 65536 threads
    k1_coef<<<512, 128>>>(x, A, Wb, bb, Wc, bc, Wd, bd);

    dim3 grid(NC, BB);
    k2_local<<<grid, 128>>>(x);
    k25_combine<<<64, 128>>>();
    k3_scan<<<grid, 128>>>(x, y);
}

// round 9
// speedup vs baseline: 1.0582x; 1.0255x over previous
#include <cuda_runtime.h>

// Problem dimensions (fixed by the reference setup)
#define BB 4
#define LL 4096
#define DD 128
#define NN 16
#define TT 32               // chunk length
#define NC (LL / TT)        // 128 chunks per batch
#define DT_OFF 0.1f
#define FUSED_GRID (BB * NC)   // 512 blocks, one per (b, chunk)
#define SXP 132             // padded x-tile row stride (floats)

typedef unsigned long long u64;

// Scratch (device globals — no allocation allowed)
__device__ __align__(16) float g_coef[BB * LL * 48];      // fallback path only
__device__ __align__(16) float g_E[BB * NC * DD * NN];    // chunk-local end states
__device__ __align__(16) float g_H0[BB * NC * DD * NN];   // carry-in state per chunk
__device__ float g_P[BB * NC * NN];                        // chunk decay products

// grid barrier state (self-resetting; gen is monotonic across graph replays)
__device__ unsigned g_bar_count = 0;
__device__ unsigned g_bar_gen = 0;

// ---------------- packed f32x2 helpers ----------------
__device__ __forceinline__ u64 fma2(u64 a, u64 b, u64 c) {
    u64 d; asm("fma.rn.f32x2 %0, %1, %2, %3;" : "=l"(d) : "l"(a), "l"(b), "l"(c));
    return d;
}
__device__ __forceinline__ u64 mul2(u64 a, u64 b) {
    u64 d; asm("mul.rn.f32x2 %0, %1, %2;" : "=l"(d) : "l"(a), "l"(b));
    return d;
}
__device__ __forceinline__ u64 pack2(float lo, float hi) {
    u64 d;
    asm("mov.b64 %0, {%1, %2};" : "=l"(d)
        : "r"(__float_as_uint(lo)), "r"(__float_as_uint(hi)));
    return d;
}
__device__ __forceinline__ float2 unpack2(u64 v) {
    unsigned int lo, hi;
    asm("mov.b64 {%0, %1}, %2;" : "=r"(lo), "=r"(hi) : "l"(v));
    return make_float2(__uint_as_float(lo), __uint_as_float(hi));
}

// ---------------- device-wide sense barrier ----------------
__device__ __forceinline__ void grid_barrier()
{
    __threadfence();                       // all threads: publish prior writes
    __syncthreads();
    if (threadIdx.x == 0) {
        unsigned gen = atomicAdd(&g_bar_gen, 0u);   // read BEFORE arriving
        __threadfence();                             // order gen-read vs arrive
        unsigned t = atomicAdd(&g_bar_count, 1u);
        if (t == gridDim.x - 1) {
            atomicExch(&g_bar_count, 0u);
            __threadfence();                         // reset visible before release
            atomicExch(&g_bar_gen, gen + 1u);
        } else {
            while (atomicAdd(&g_bar_gen, 0u) == gen) __nanosleep(64);
        }
    }
    __syncthreads();
}

// ===========================================================================
// FUSED persistent kernel: one block per (b, chunk).
//   Phase A: W+x -> smem, projection GEMM -> coef in smem, zero-init scan -> E,P
//   barrier
//   Phase B: inter-chunk combine (8192 threads) -> H0
//   barrier
//   Phase C: re-scan with carry-in using smem-resident coef + x -> y
// ===========================================================================
__global__ __launch_bounds__(128, 4) void fused_s6(
    const float* __restrict__ x,
    const float* __restrict__ A,
    const float* __restrict__ Wb, const float* __restrict__ bb,
    const float* __restrict__ Wc, const float* __restrict__ bc,
    const float* __restrict__ Wd, const float* __restrict__ bd,
    float* __restrict__ y)
{
    __shared__ __align__(16) float sW[33 * 128];   // 16896 B
    __shared__ __align__(16) float sx[TT * SXP];   // 16896 B (padded rows)
    __shared__ __align__(16) float sc[TT * 48];    //  6144 B
    __shared__ float sb[33];
    __shared__ float sA[16];

    int tid = threadIdx.x;
    int blk = blockIdx.x;
    int c = blk & (NC - 1);
    int b = blk >> 7;                 // NC = 128

    // ---- load W / biases / A into smem ----
    for (int i = tid; i < 2048; i += 128) {
        sW[i]        = Wb[i];
        sW[2048 + i] = Wc[i];
    }
    sW[4096 + tid] = Wd[tid];
    if (tid < 16) { sb[tid] = bb[tid]; sb[16 + tid] = bc[tid]; sA[tid] = A[tid]; }
    if (tid == 0) sb[32] = bd[0];

    // ---- load x tile (TT x 128) into padded smem ----
    const float4* xg = (const float4*)(x + (size_t)(b * LL + c * TT) * DD);
#pragma unroll
    for (int i = 0; i < 8; i++) {
        int idx = i * 128 + tid;          // float4 index, 1024 total
        float4 v = xg[idx];
        int t   = idx >> 5;               // 32 float4 per row
        int col = (idx & 31) << 2;
        *(float4*)&sx[t * SXP + col] = v;
    }
    __syncthreads();

    // ---- projection GEMM: 4 threads per position, kk-rotation (bank-safe) ----
    {
        int pl = tid >> 2;                // position within chunk, 0..31
        int q  = tid & 3;                 // quarter of the 128-dim dot

        float acc[33];
#pragma unroll
        for (int j = 0; j < 33; j++) acc[j] = 0.f;

        const float4* xr = (const float4*)(sx + pl * SXP + q * 32);
        const float4* W4 = (const float4*)sW;

#pragma unroll
        for (int kk = 0; kk < 8; kk++) {
            int kkr = (kk + 2 * q) & 7;   // rotate -> conflict-free W banks
            float4 xv = xr[kkr];
            int basei = q * 8 + kkr;
#pragma unroll
            for (int j = 0; j < 33; j++) {
                float4 wv = W4[j * 32 + basei];
                acc[j] = fmaf(xv.w, wv.w, fmaf(xv.z, wv.z,
                         fmaf(xv.y, wv.y, fmaf(xv.x, wv.x, acc[j]))));
            }
        }
#pragma unroll
        for (int j = 0; j < 33; j++) {
            acc[j] += __shfl_down_sync(0xffffffffu, acc[j], 2);
            acc[j] += __shfl_down_sync(0xffffffffu, acc[j], 1);
        }

        if (q == 0) {
            float z = acc[32] + sb[32];
            float delta = fmaxf(z, 0.f) + log1pf(expf(-fabsf(z))) + DT_OFF;
            float* row = sc + pl * 48;
#pragma unroll
            for (int n = 0; n < 16; n++) {
                float da = delta * sA[n];
                row[n]      = expf(da);
                row[16 + n] = (1.0f - expf(-da)) * delta * (acc[n] + sb[n]);
                row[32 + n] = acc[16 + n] + sb[16 + n];
            }
        }
    }
    __syncthreads();

    // ---- Phase A: zero-init chunk scan -> E, P ----
    {
        int d = tid;
        u64 h[8];
#pragma unroll
        for (int i = 0; i < 8; i++) h[i] = 0ull;

#pragma unroll 4
        for (int t = 0; t < TT; t++) {
            float xt = sx[t * SXP + d];
            u64 x2 = pack2(xt, xt);
            const ulonglong2* row = (const ulonglong2*)(sc + t * 48);
#pragma unroll
            for (int i = 0; i < 4; i++) {
                ulonglong2 e2 = row[i];
                ulonglong2 w2 = row[4 + i];
                h[2 * i]     = fma2(e2.x, h[2 * i],     mul2(w2.x, x2));
                h[2 * i + 1] = fma2(e2.y, h[2 * i + 1], mul2(w2.y, x2));
            }
        }

        ulonglong2* Eo = (ulonglong2*)(g_E + (size_t)((b * NC + c) * DD + d) * NN);
#pragma unroll
        for (int i = 0; i < 4; i++) {
            ulonglong2 v; v.x = h[2 * i]; v.y = h[2 * i + 1];
            Eo[i] = v;
        }
        if (d < 16) {
            float p = 1.f;
#pragma unroll
            for (int t = 0; t < TT; t++) p *= sc[t * 48 + d];
            g_P[(b * NC + c) * NN + d] = p;
        }
    }

    grid_barrier();

    // ---- Phase B: inter-chunk combine (first 8192 threads) ----
    {
        int gt = blk * 128 + tid;
        if (gt < BB * DD * NN) {
            int bb_ = gt >> 11;            // / (D*N)
            int r   = gt & 2047;           // d*16 + n
            int n   = r & 15;
            float h = 0.f;
            const float* P = g_P + bb_ * NC * NN + n;
            size_t o = (size_t)bb_ * NC * (DD * NN) + r;
#pragma unroll 16
            for (int cc = 0; cc < NC; cc++) {
                g_H0[o] = h;
                h = fmaf(__ldcg(P + cc * NN), h, __ldcg(g_E + o));
                o += DD * NN;
            }
        }
    }

    grid_barrier();

    // ---- Phase C: carry-in scan using smem-resident coef + x -> y ----
    {
        int d = tid;
        u64 h[8];
        const uint4* hi = (const uint4*)(g_H0 + (size_t)((b * NC + c) * DD + d) * NN);
#pragma unroll
        for (int i = 0; i < 4; i++) {
            uint4 v = __ldcg(hi + i);
            h[2 * i]     = pack2(__uint_as_float(v.x), __uint_as_float(v.y));
            h[2 * i + 1] = pack2(__uint_as_float(v.z), __uint_as_float(v.w));
        }

        float* yp = y + (size_t)(b * LL + c * TT) * DD + d;

#pragma unroll 4
        for (int t = 0; t < TT; t++) {
            float xt = sx[t * SXP + d];
            u64 x2 = pack2(xt, xt);
            const ulonglong2* row = (const ulonglong2*)(sc + t * 48);

            u64 a0 = 0ull, a1 = 0ull, a2 = 0ull, a3 = 0ull;
#pragma unroll
            for (int i = 0; i < 4; i++) {
                ulonglong2 e2 = row[i];
                ulonglong2 w2 = row[4 + i];
                ulonglong2 c2 = row[8 + i];
                h[2 * i]     = fma2(e2.x, h[2 * i],     mul2(w2.x, x2));
                h[2 * i + 1] = fma2(e2.y, h[2 * i + 1], mul2(w2.y, x2));
                if (i == 0)      { a0 = fma2(c2.x, h[0], a0); a1 = fma2(c2.y, h[1], a1); }
                else if (i == 1) { a2 = fma2(c2.x, h[2], a2); a3 = fma2(c2.y, h[3], a3); }
                else if (i == 2) { a0 = fma2(c2.x, h[4], a0); a1 = fma2(c2.y, h[5], a1); }
                else             { a2 = fma2(c2.x, h[6], a2); a3 = fma2(c2.y, h[7], a3); }
            }
            float2 p0 = unpack2(a0), p1 = unpack2(a1), p2 = unpack2(a2), p3 = unpack2(a3);
            yp[t * DD] = ((p0.x + p0.y) + (p1.x + p1.y)) + ((p2.x + p2.y) + (p3.x + p3.y));
        }
    }
}

// ===========================================================================
// Fallback path (proven 4-kernel pipeline from R8) — used only if the fused
// kernel cannot be fully co-resident on this device.
// ===========================================================================
__global__ __launch_bounds__(128) void k1_coef(
    const float* __restrict__ x,
    const float* __restrict__ A,
    const float* __restrict__ Wb, const float* __restrict__ bb,
    const float* __restrict__ Wc, const float* __restrict__ bc,
    const float* __restrict__ Wd, const float* __restrict__ bd)
{
    __shared__ __align__(16) float sW[33 * 128];
    __shared__ float sb[33];
    __shared__ float sA[16];

    int tid = threadIdx.x;
    for (int i = tid; i < 2048; i += 128) {
        sW[i]        = Wb[i];
        sW[2048 + i] = Wc[i];
    }
    sW[4096 + tid] = Wd[tid];
    if (tid < 16) { sb[tid] = bb[tid]; sb[16 + tid] = bc[tid]; sA[tid] = A[tid]; }
    if (tid == 0) sb[32] = bd[0];
    __syncthreads();

    int g   = blockIdx.x * 128 + tid;
    int pos = g >> 2;
    int q   = g & 3;

    float acc[33];
#pragma unroll
    for (int j = 0; j < 33; j++) acc[j] = 0.f;

    const float4* xr = (const float4*)(x + (size_t)pos * DD + q * 32);
    const float4* W4 = (const float4*)sW;

#pragma unroll
    for (int kk = 0; kk < 8; kk++) {
        int kkr = (kk + 2 * q) & 7;
        float4 xv = xr[kkr];
        int basei = q * 8 + kkr;
#pragma unroll
        for (int j = 0; j < 33; j++) {
            float4 wv = W4[j * 32 + basei];
            acc[j] = fmaf(xv.w, wv.w, fmaf(xv.z, wv.z,
                     fmaf(xv.y, wv.y, fmaf(xv.x, wv.x, acc[j]))));
        }
    }
#pragma unroll
    for (int j = 0; j < 33; j++) {
        acc[j] += __shfl_down_sync(0xffffffffu, acc[j], 2);
        acc[j] += __shfl_down_sync(0xffffffffu, acc[j], 1);
    }

    if (q == 0) {
        float z = acc[32] + sb[32];
        float delta = fmaxf(z, 0.f) + log1pf(expf(-fabsf(z))) + DT_OFF;
        float out[48];
#pragma unroll
        for (int n = 0; n < 16; n++) {
            float da = delta * sA[n];
            out[n]      = expf(da);
            out[16 + n] = (1.0f - expf(-da)) * delta * (acc[n] + sb[n]);
            out[32 + n] = acc[16 + n] + sb[16 + n];
        }
        float4* o = (float4*)(g_coef + (size_t)pos * 48);
        const float4* ov = (const float4*)out;
#pragma unroll
        for (int i = 0; i < 12; i++) o[i] = ov[i];
    }
}

__global__ __launch_bounds__(128) void k2_local(const float* __restrict__ x)
{
    __shared__ __align__(16) float sc[TT * 48];
    int c = blockIdx.x, b = blockIdx.y, d = threadIdx.x;

    float xv[TT];
    const float* xp = x + (size_t)(b * LL + c * TT) * DD + d;
#pragma unroll
    for (int t = 0; t < TT; t++) xv[t] = xp[t * DD];

    const float4* csrc = (const float4*)(g_coef + (size_t)(b * LL + c * TT) * 48);
    float4* cdst = (float4*)sc;
#pragma unroll
    for (int i = 0; i < 3; i++) cdst[d + 128 * i] = csrc[d + 128 * i];
    __syncthreads();

    u64 h[8];
#pragma unroll
    for (int i = 0; i < 8; i++) h[i] = 0ull;

#pragma unroll 4
    for (int t = 0; t < TT; t++) {
        u64 x2 = pack2(xv[t], xv[t]);
        const ulonglong2* row = (const ulonglong2*)(sc + t * 48);
#pragma unroll
        for (int i = 0; i < 4; i++) {
            ulonglong2 e2 = row[i];
            ulonglong2 w2 = row[4 + i];
            h[2 * i]     = fma2(e2.x, h[2 * i],     mul2(w2.x, x2));
            h[2 * i + 1] = fma2(e2.y, h[2 * i + 1], mul2(w2.y, x2));
        }
    }

    ulonglong2* Eo = (ulonglong2*)(g_E + (size_t)((b * NC + c) * DD + d) * NN);
#pragma unroll
    for (int i = 0; i < 4; i++) {
        ulonglong2 v; v.x = h[2 * i]; v.y = h[2 * i + 1];
        Eo[i] = v;
    }
    if (d < 16) {
        float p = 1.f;
#pragma unroll
        for (int t = 0; t < TT; t++) p *= sc[t * 48 + d];
        g_P[(b * NC + c) * NN + d] = p;
    }
}

__global__ __launch_bounds__(128) void k25_combine()
{
    int idx = blockIdx.x * 128 + threadIdx.x;
    int b = idx >> 11;
    int r = idx & 2047;
    int n = r & 15;
    float h = 0.f;
    const float* __restrict__ P = g_P + b * NC * NN + n;
    size_t o = (size_t)b * NC * (DD * NN) + r;
#pragma unroll 16
    for (int c = 0; c < NC; c++) {
        g_H0[o] = h;
        h = fmaf(P[c * NN], h, g_E[o]);
        o += DD * NN;
    }
}

__global__ __launch_bounds__(128) void k3_scan(const float* __restrict__ x,
                                               float* __restrict__ y)
{
    __shared__ __align__(16) float sc[TT * 48];
    int c = blockIdx.x, b = blockIdx.y, d = threadIdx.x;

    float xv[TT];
    const float* xp = x + (size_t)(b * LL + c * TT) * DD + d;
#pragma unroll
    for (int t = 0; t < TT; t++) xv[t] = xp[t * DD];

    const float4* csrc = (const float4*)(g_coef + (size_t)(b * LL + c * TT) * 48);
    float4* cdst = (float4*)sc;
#pragma unroll
    for (int i = 0; i < 3; i++) cdst[d + 128 * i] = csrc[d + 128 * i];

    u64 h[8];
    const ulonglong2* hi = (const ulonglong2*)(g_H0 + (size_t)((b * NC + c) * DD + d) * NN);
#pragma unroll
    for (int i = 0; i < 4; i++) {
        ulonglong2 v = hi[i];
        h[2 * i] = v.x; h[2 * i + 1] = v.y;
    }
    __syncthreads();

    float* yp = y + (size_t)(b * LL + c * TT) * DD + d;

#pragma unroll 4
    for (int t = 0; t < TT; t++) {
        u64 x2 = pack2(xv[t], xv[t]);
        const ulonglong2* row = (const ulonglong2*)(sc + t * 48);

        u64 a0 = 0ull, a1 = 0ull, a2 = 0ull, a3 = 0ull;
#pragma unroll
        for (int i = 0; i < 4; i++) {
            ulonglong2 e2 = row[i];
            ulonglong2 w2 = row[4 + i];
            ulonglong2 c2 = row[8 + i];
            h[2 * i]     = fma2(e2.x, h[2 * i],     mul2(w2.x, x2));
            h[2 * i + 1] = fma2(e2.y, h[2 * i + 1], mul2(w2.y, x2));
            if (i == 0)      { a0 = fma2(c2.x, h[0], a0); a1 = fma2(c2.y, h[1], a1); }
            else if (i == 1) { a2 = fma2(c2.x, h[2], a2); a3 = fma2(c2.y, h[3], a3); }
            else if (i == 2) { a0 = fma2(c2.x, h[4], a0); a1 = fma2(c2.y, h[5], a1); }
            else             { a2 = fma2(c2.x, h[6], a2); a3 = fma2(c2.y, h[7], a3); }
        }
        float2 p0 = unpack2(a0), p1 = unpack2(a1), p2 = unpack2(a2), p3 = unpack2(a3);
        yp[t * DD] = ((p0.x + p0.y) + (p1.x + p1.y)) + ((p2.x + p2.y) + (p3.x + p3.y));
    }
}

// ---------------------------------------------------------------------------
extern "C" void kernel_launch(void* const* d_in, const int* in_sizes, int n_in,
                              void* d_out, int out_size)
{
    const float* x  = (const float*)d_in[0];
    const float* A  = (const float*)d_in[1];
    const float* Wb = (const float*)d_in[2];
    const float* bb = (const float*)d_in[3];
    const float* Wc = (const float*)d_in[4];
    const float* bc = (const float*)d_in[5];
    const float* Wd = (const float*)d_in[6];
    const float* bd = (const float*)d_in[7];
    float* y = (float*)d_out;

    // The fused kernel's grid barrier requires all FUSED_GRID blocks to be
    // co-resident. Verify via the occupancy API; otherwise use the safe path.
    int dev = 0, nsm = 0, maxb = 0;
    cudaGetDevice(&dev);
    cudaDeviceGetAttribute(&nsm, cudaDevAttrMultiProcessorCount, dev);
    cudaOccupancyMaxActiveBlocksPerMultiprocessor(&maxb, fused_s6, 128, 0);

    if ((long long)nsm * maxb >= FUSED_GRID) {
        fused_s6<<<FUSED_GRID, 128>>>(x, A, Wb, bb, Wc, bc, Wd, bd, y);
    } else {
        k1_coef<<<512, 128>>>(x, A, Wb, bb, Wc, bc, Wd, bd);
        dim3 grid(NC, BB);
        k2_local<<<grid, 128>>>(x);
        k25_combine<<<64, 128>>>();
        k3_scan<<<grid, 128>>>(x, y);
    }
}

// round 10
// speedup vs baseline: 1.0940x; 1.0339x over previous
#include <cuda_runtime.h>

// Problem dimensions (fixed by the reference setup)
#define BB 4
#define LL 4096
#define DD 128
#define NN 16
#define TT 32               // chunk length
#define NC (LL / TT)        // 128 chunks per batch
#define DT_OFF 0.1f
#define FUSED_GRID (BB * NC)   // 512 blocks, one per (b, chunk)
#define SXP 132             // padded x-tile row stride (floats)

typedef unsigned long long u64;

// Scratch (device globals — no allocation allowed)
__device__ __align__(16) float g_coef[BB * LL * 48];      // fallback path only
__device__ __align__(16) float g_E[BB * NC * DD * NN];    // chunk-local end states
__device__ __align__(16) float g_H0[BB * NC * DD * NN];   // carry-in state per chunk
__device__ float g_P[BB * NC * NN];                        // chunk decay products

// grid barrier state (gen is monotonic across graph replays; count self-resets)
__device__ unsigned g_bar_count = 0;
__device__ volatile unsigned g_bar_gen = 0;

// ---------------- packed f32x2 helpers ----------------
__device__ __forceinline__ u64 fma2(u64 a, u64 b, u64 c) {
    u64 d; asm("fma.rn.f32x2 %0, %1, %2, %3;" : "=l"(d) : "l"(a), "l"(b), "l"(c));
    return d;
}
__device__ __forceinline__ u64 mul2(u64 a, u64 b) {
    u64 d; asm("mul.rn.f32x2 %0, %1, %2;" : "=l"(d) : "l"(a), "l"(b));
    return d;
}
__device__ __forceinline__ u64 pack2(float lo, float hi) {
    u64 d;
    asm("mov.b64 %0, {%1, %2};" : "=l"(d)
        : "r"(__float_as_uint(lo)), "r"(__float_as_uint(hi)));
    return d;
}
__device__ __forceinline__ float2 unpack2(u64 v) {
    unsigned int lo, hi;
    asm("mov.b64 {%0, %1}, %2;" : "=r"(lo), "=r"(hi) : "l"(v));
    return make_float2(__uint_as_float(lo), __uint_as_float(hi));
}

// ---------------- device-wide sense barrier ----------------
// Arrivals: one atomicAdd per block (pipelined RMW, ~0.85 cyc/op).
// Waiting: plain VOLATILE loads of the generation word — reads to one L2
// line are broadcast-served, they do NOT serialize the atomic unit the way
// atomicAdd(ptr,0) polling does (the R9 failure mode).
__device__ __forceinline__ void grid_barrier()
{
    __syncthreads();                       // block-local: everyone done
    if (threadIdx.x == 0) {
        __threadfence();                   // publish this block's writes
        unsigned gen = g_bar_gen;          // read BEFORE arriving
        unsigned t = atomicAdd(&g_bar_count, 1u);
        if (t == gridDim.x - 1) {
            g_bar_count = 0u;              // safe: all arrived, none re-arm yet
            __threadfence();               // reset visible before release
            atomicExch((unsigned*)&g_bar_gen, gen + 1u);
        } else {
            while (g_bar_gen == gen) __nanosleep(128);
        }
        __threadfence();                   // acquire: see other blocks' writes
    }
    __syncthreads();
}

// ===========================================================================
// FUSED persistent kernel: one block per (b, chunk).
//   Phase A: W+x -> smem, projection GEMM -> coef in smem, zero-init scan -> E,P
//   barrier
//   Phase B: inter-chunk combine, PERFECTLY BALANCED: block (b,c) combines
//            state row d=c for all n (threads 0..15), serial over 128 chunks
//   barrier
//   Phase C: re-scan with carry-in using smem-resident coef + x -> y
// ===========================================================================
__global__ __launch_bounds__(128, 4) void fused_s6(
    const float* __restrict__ x,
    const float* __restrict__ A,
    const float* __restrict__ Wb, const float* __restrict__ bb,
    const float* __restrict__ Wc, const float* __restrict__ bc,
    const float* __restrict__ Wd, const float* __restrict__ bd,
    float* __restrict__ y)
{
    __shared__ __align__(16) float sW[33 * 128];   // 16896 B
    __shared__ __align__(16) float sx[TT * SXP];   // 16896 B (padded rows)
    __shared__ __align__(16) float sc[TT * 48];    //  6144 B
    __shared__ float sb[33];
    __shared__ float sA[16];

    int tid = threadIdx.x;
    int blk = blockIdx.x;
    int c = blk & (NC - 1);
    int b = blk >> 7;                 // NC = 128

    // ---- load W / biases / A into smem ----
    for (int i = tid; i < 2048; i += 128) {
        sW[i]        = Wb[i];
        sW[2048 + i] = Wc[i];
    }
    sW[4096 + tid] = Wd[tid];
    if (tid < 16) { sb[tid] = bb[tid]; sb[16 + tid] = bc[tid]; sA[tid] = A[tid]; }
    if (tid == 0) sb[32] = bd[0];

    // ---- load x tile (TT x 128) into padded smem ----
    const float4* xg = (const float4*)(x + (size_t)(b * LL + c * TT) * DD);
#pragma unroll
    for (int i = 0; i < 8; i++) {
        int idx = i * 128 + tid;          // float4 index, 1024 total
        float4 v = xg[idx];
        int t   = idx >> 5;               // 32 float4 per row
        int col = (idx & 31) << 2;
        *(float4*)&sx[t * SXP + col] = v;
    }
    __syncthreads();

    // ---- projection GEMM: 4 threads per position, kk-rotation (bank-safe) ----
    {
        int pl = tid >> 2;                // position within chunk, 0..31
        int q  = tid & 3;                 // quarter of the 128-dim dot

        float acc[33];
#pragma unroll
        for (int j = 0; j < 33; j++) acc[j] = 0.f;

        const float4* xr = (const float4*)(sx + pl * SXP + q * 32);
        const float4* W4 = (const float4*)sW;

#pragma unroll
        for (int kk = 0; kk < 8; kk++) {
            int kkr = (kk + 2 * q) & 7;   // rotate -> conflict-free W banks
            float4 xv = xr[kkr];
            int basei = q * 8 + kkr;
#pragma unroll
            for (int j = 0; j < 33; j++) {
                float4 wv = W4[j * 32 + basei];
                acc[j] = fmaf(xv.w, wv.w, fmaf(xv.z, wv.z,
                         fmaf(xv.y, wv.y, fmaf(xv.x, wv.x, acc[j]))));
            }
        }
#pragma unroll
        for (int j = 0; j < 33; j++) {
            acc[j] += __shfl_down_sync(0xffffffffu, acc[j], 2);
            acc[j] += __shfl_down_sync(0xffffffffu, acc[j], 1);
        }

        if (q == 0) {
            float z = acc[32] + sb[32];
            float delta = fmaxf(z, 0.f) + log1pf(expf(-fabsf(z))) + DT_OFF;
            float* row = sc + pl * 48;
#pragma unroll
            for (int n = 0; n < 16; n++) {
                float da = delta * sA[n];
                row[n]      = expf(da);
                row[16 + n] = (1.0f - expf(-da)) * delta * (acc[n] + sb[n]);
                row[32 + n] = acc[16 + n] + sb[16 + n];
            }
        }
    }
    __syncthreads();

    // ---- Phase A: zero-init chunk scan -> E, P ----
    {
        int d = tid;
        u64 h[8];
#pragma unroll
        for (int i = 0; i < 8; i++) h[i] = 0ull;

#pragma unroll 4
        for (int t = 0; t < TT; t++) {
            float xt = sx[t * SXP + d];
            u64 x2 = pack2(xt, xt);
            const ulonglong2* row = (const ulonglong2*)(sc + t * 48);
#pragma unroll
            for (int i = 0; i < 4; i++) {
                ulonglong2 e2 = row[i];
                ulonglong2 w2 = row[4 + i];
                h[2 * i]     = fma2(e2.x, h[2 * i],     mul2(w2.x, x2));
                h[2 * i + 1] = fma2(e2.y, h[2 * i + 1], mul2(w2.y, x2));
            }
        }

        ulonglong2* Eo = (ulonglong2*)(g_E + (size_t)((b * NC + c) * DD + d) * NN);
#pragma unroll
        for (int i = 0; i < 4; i++) {
            ulonglong2 v; v.x = h[2 * i]; v.y = h[2 * i + 1];
            Eo[i] = v;
        }
        if (d < 16) {
            float p = 1.f;
#pragma unroll
            for (int t = 0; t < TT; t++) p *= sc[t * 48 + d];
            g_P[(b * NC + c) * NN + d] = p;
        }
    }

    grid_barrier();

    // ---- Phase B: balanced inter-chunk combine ----
    // Block (b,c) owns state row d=c of batch b; threads 0..15 = n.
    // Serial over all NC chunks:  H0[cc] = h;  h = P[cc]*h + E[cc].
    if (tid < NN) {
        int n = tid;
        float h = 0.f;
        const float* P = g_P + b * NC * NN + n;
        size_t o = (size_t)b * NC * (DD * NN) + c * NN + n;
#pragma unroll 16
        for (int cc = 0; cc < NC; cc++) {
            g_H0[o] = h;
            h = fmaf(__ldcg(P + cc * NN), h, __ldcg(g_E + o));
            o += DD * NN;
        }
    }

    grid_barrier();

    // ---- Phase C: carry-in scan using smem-resident coef + x -> y ----
    {
        int d = tid;
        u64 h[8];
        const uint4* hi = (const uint4*)(g_H0 + (size_t)((b * NC + c) * DD + d) * NN);
#pragma unroll
        for (int i = 0; i < 4; i++) {
            uint4 v = __ldcg(hi + i);
            h[2 * i]     = pack2(__uint_as_float(v.x), __uint_as_float(v.y));
            h[2 * i + 1] = pack2(__uint_as_float(v.z), __uint_as_float(v.w));
        }

        float* yp = y + (size_t)(b * LL + c * TT) * DD + d;

#pragma unroll 4
        for (int t = 0; t < TT; t++) {
            float xt = sx[t * SXP + d];
            u64 x2 = pack2(xt, xt);
            const ulonglong2* row = (const ulonglong2*)(sc + t * 48);

            u64 a0 = 0ull, a1 = 0ull, a2 = 0ull, a3 = 0ull;
#pragma unroll
            for (int i = 0; i < 4; i++) {
                ulonglong2 e2 = row[i];
                ulonglong2 w2 = row[4 + i];
                ulonglong2 c2 = row[8 + i];
                h[2 * i]     = fma2(e2.x, h[2 * i],     mul2(w2.x, x2));
                h[2 * i + 1] = fma2(e2.y, h[2 * i + 1], mul2(w2.y, x2));
                if (i == 0)      { a0 = fma2(c2.x, h[0], a0); a1 = fma2(c2.y, h[1], a1); }
                else if (i == 1) { a2 = fma2(c2.x, h[2], a2); a3 = fma2(c2.y, h[3], a3); }
                else if (i == 2) { a0 = fma2(c2.x, h[4], a0); a1 = fma2(c2.y, h[5], a1); }
                else             { a2 = fma2(c2.x, h[6], a2); a3 = fma2(c2.y, h[7], a3); }
            }
            float2 p0 = unpack2(a0), p1 = unpack2(a1), p2 = unpack2(a2), p3 = unpack2(a3);
            yp[t * DD] = ((p0.x + p0.y) + (p1.x + p1.y)) + ((p2.x + p2.y) + (p3.x + p3.y));
        }
    }
}

// ===========================================================================
// Fallback path (proven 4-kernel pipeline) — used only if the fused kernel
// cannot be fully co-resident on this device.
// ===========================================================================
__global__ __launch_bounds__(128) void k1_coef(
    const float* __restrict__ x,
    const float* __restrict__ A,
    const float* __restrict__ Wb, const float* __restrict__ bb,
    const float* __restrict__ Wc, const float* __restrict__ bc,
    const float* __restrict__ Wd, const float* __restrict__ bd)
{
    __shared__ __align__(16) float sW[33 * 128];
    __shared__ float sb[33];
    __shared__ float sA[16];

    int tid = threadIdx.x;
    for (int i = tid; i < 2048; i += 128) {
        sW[i]        = Wb[i];
        sW[2048 + i] = Wc[i];
    }
    sW[4096 + tid] = Wd[tid];
    if (tid < 16) { sb[tid] = bb[tid]; sb[16 + tid] = bc[tid]; sA[tid] = A[tid]; }
    if (tid == 0) sb[32] = bd[0];
    __syncthreads();

    int g   = blockIdx.x * 128 + tid;
    int pos = g >> 2;
    int q   = g & 3;

    float acc[33];
#pragma unroll
    for (int j = 0; j < 33; j++) acc[j] = 0.f;

    const float4* xr = (const float4*)(x + (size_t)pos * DD + q * 32);
    const float4* W4 = (const float4*)sW;

#pragma unroll
    for (int kk = 0; kk < 8; kk++) {
        int kkr = (kk + 2 * q) & 7;
        float4 xv = xr[kkr];
        int basei = q * 8 + kkr;
#pragma unroll
        for (int j = 0; j < 33; j++) {
            float4 wv = W4[j * 32 + basei];
            acc[j] = fmaf(xv.w, wv.w, fmaf(xv.z, wv.z,
                     fmaf(xv.y, wv.y, fmaf(xv.x, wv.x, acc[j]))));
        }
    }
#pragma unroll
    for (int j = 0; j < 33; j++) {
        acc[j] += __shfl_down_sync(0xffffffffu, acc[j], 2);
        acc[j] += __shfl_down_sync(0xffffffffu, acc[j], 1);
    }

    if (q == 0) {
        float z = acc[32] + sb[32];
        float delta = fmaxf(z, 0.f) + log1pf(expf(-fabsf(z))) + DT_OFF;
        float out[48];
#pragma unroll
        for (int n = 0; n < 16; n++) {
            float da = delta * sA[n];
            out[n]      = expf(da);
            out[16 + n] = (1.0f - expf(-da)) * delta * (acc[n] + sb[n]);
            out[32 + n] = acc[16 + n] + sb[16 + n];
        }
        float4* o = (float4*)(g_coef + (size_t)pos * 48);
        const float4* ov = (const float4*)out;
#pragma unroll
        for (int i = 0; i < 12; i++) o[i] = ov[i];
    }
}

__global__ __launch_bounds__(128) void k2_local(const float* __restrict__ x)
{
    __shared__ __align__(16) float sc[TT * 48];
    int c = blockIdx.x, b = blockIdx.y, d = threadIdx.x;

    float xv[TT];
    const float* xp = x + (size_t)(b * LL + c * TT) * DD + d;
#pragma unroll
    for (int t = 0; t < TT; t++) xv[t] = xp[t * DD];

    const float4* csrc = (const float4*)(g_coef + (size_t)(b * LL + c * TT) * 48);
    float4* cdst = (float4*)sc;
#pragma unroll
    for (int i = 0; i < 3; i++) cdst[d + 128 * i] = csrc[d + 128 * i];
    __syncthreads();

    u64 h[8];
#pragma unroll
    for (int i = 0; i < 8; i++) h[i] = 0ull;

#pragma unroll 4
    for (int t = 0; t < TT; t++) {
        u64 x2 = pack2(xv[t], xv[t]);
        const ulonglong2* row = (const ulonglong2*)(sc + t * 48);
#pragma unroll
        for (int i = 0; i < 4; i++) {
            ulonglong2 e2 = row[i];
            ulonglong2 w2 = row[4 + i];
            h[2 * i]     = fma2(e2.x, h[2 * i],     mul2(w2.x, x2));
            h[2 * i + 1] = fma2(e2.y, h[2 * i + 1], mul2(w2.y, x2));
        }
    }

    ulonglong2* Eo = (ulonglong2*)(g_E + (size_t)((b * NC + c) * DD + d) * NN);
#pragma unroll
    for (int i = 0; i < 4; i++) {
        ulonglong2 v; v.x = h[2 * i]; v.y = h[2 * i + 1];
        Eo[i] = v;
    }
    if (d < 16) {
        float p = 1.f;
#pragma unroll
        for (int t = 0; t < TT; t++) p *= sc[t * 48 + d];
        g_P[(b * NC + c) * NN + d] = p;
    }
}

__global__ __launch_bounds__(128) void k25_combine()
{
    int idx = blockIdx.x * 128 + threadIdx.x;
    int b = idx >> 11;
    int r = idx & 2047;
    int n = r & 15;
    float h = 0.f;
    const float* __restrict__ P = g_P + b * NC * NN + n;
    size_t o = (size_t)b * NC * (DD * NN) + r;
#pragma unroll 16
    for (int c = 0; c < NC; c++) {
        g_H0[o] = h;
        h = fmaf(P[c * NN], h, g_E[o]);
        o += DD * NN;
    }
}

__global__ __launch_bounds__(128) void k3_scan(const float* __restrict__ x,
                                               float* __restrict__ y)
{
    __shared__ __align__(16) float sc[TT * 48];
    int c = blockIdx.x, b = blockIdx.y, d = threadIdx.x;

    float xv[TT];
    const float* xp = x + (size_t)(b * LL + c * TT) * DD + d;
#pragma unroll
    for (int t = 0; t < TT; t++) xv[t] = xp[t * DD];

    const float4* csrc = (const float4*)(g_coef + (size_t)(b * LL + c * TT) * 48);
    float4* cdst = (float4*)sc;
#pragma unroll
    for (int i = 0; i < 3; i++) cdst[d + 128 * i] = csrc[d + 128 * i];

    u64 h[8];
    const ulonglong2* hi = (const ulonglong2*)(g_H0 + (size_t)((b * NC + c) * DD + d) * NN);
#pragma unroll
    for (int i = 0; i < 4; i++) {
        ulonglong2 v = hi[i];
        h[2 * i] = v.x; h[2 * i + 1] = v.y;
    }
    __syncthreads();

    float* yp = y + (size_t)(b * LL + c * TT) * DD + d;

#pragma unroll 4
    for (int t = 0; t < TT; t++) {
        u64 x2 = pack2(xv[t], xv[t]);
        const ulonglong2* row = (const ulonglong2*)(sc + t * 48);

        u64 a0 = 0ull, a1 = 0ull, a2 = 0ull, a3 = 0ull;
#pragma unroll
        for (int i = 0; i < 4; i++) {
            ulonglong2 e2 = row[i];
            ulonglong2 w2 = row[4 + i];
            ulonglong2 c2 = row[8 + i];
            h[2 * i]     = fma2(e2.x, h[2 * i],     mul2(w2.x, x2));
            h[2 * i + 1] = fma2(e2.y, h[2 * i + 1], mul2(w2.y, x2));
            if (i == 0)      { a0 = fma2(c2.x, h[0], a0); a1 = fma2(c2.y, h[1], a1); }
            else if (i == 1) { a2 = fma2(c2.x, h[2], a2); a3 = fma2(c2.y, h[3], a3); }
            else if (i == 2) { a0 = fma2(c2.x, h[4], a0); a1 = fma2(c2.y, h[5], a1); }
            else             { a2 = fma2(c2.x, h[6], a2); a3 = fma2(c2.y, h[7], a3); }
        }
        float2 p0 = unpack2(a0), p1 = unpack2(a1), p2 = unpack2(a2), p3 = unpack2(a3);
        yp[t * DD] = ((p0.x + p0.y) + (p1.x + p1.y)) + ((p2.x + p2.y) + (p3.x + p3.y));
    }
}

// ---------------------------------------------------------------------------
extern "C" void kernel_launch(void* const* d_in, const int* in_sizes, int n_in,
                              void* d_out, int out_size)
{
    const float* x  = (const float*)d_in[0];
    const float* A  = (const float*)d_in[1];
    const float* Wb = (const float*)d_in[2];
    const float* bb = (const float*)d_in[3];
    const float* Wc = (const float*)d_in[4];
    const float* bc = (const float*)d_in[5];
    const float* Wd = (const float*)d_in[6];
    const float* bd = (const float*)d_in[7];
    float* y = (float*)d_out;

    // The fused kernel's grid barrier requires all FUSED_GRID blocks to be
    // co-resident. Verify via the occupancy API; otherwise use the safe path.
    int dev = 0, nsm = 0, maxb = 0;
    cudaGetDevice(&dev);
    cudaDeviceGetAttribute(&nsm, cudaDevAttrMultiProcessorCount, dev);
    cudaOccupancyMaxActiveBlocksPerMultiprocessor(&maxb, fused_s6, 128, 0);

    if ((long long)nsm * maxb >= FUSED_GRID) {
        fused_s6<<<FUSED_GRID, 128>>>(x, A, Wb, bb, Wc, bc, Wd, bd, y);
    } else {
        k1_coef<<<512, 128>>>(x, A, Wb, bb, Wc, bc, Wd, bd);
        dim3 grid(NC, BB);
        k2_local<<<grid, 128>>>(x);
        k25_combine<<<64, 128>>>();
        k3_scan<<<grid, 128>>>(x, y);
    }
}